// round 1
// baseline (speedup 1.0000x reference)
#include <cuda_runtime.h>
#include <cuda_bf16.h>

#define KK 7
#define C1 21
#define NBINS 49            // KK*KK
#define NCH 1029            // NBINS*C1
#define HF 128
#define WF 128
#define PLANE (HF*WF)       // 16384
#define FEAT_STRIDE 30

// One block per ROI. Thread t handles flat channels c = t, t+256, ...
// c decomposes as c = g*C1 + cc with g = j*KK + l (bin), cc = class.
// Bin (j,l) reads ONLY its own channel plane over its own sub-rectangle:
//   y in [ymin + j*ystep, +ystep), x in [xmin + l*xstep, +xstep)
__global__ __launch_bounds__(256)
void psroi_scores_kernel(const float* __restrict__ fmap,
                         const int* __restrict__ rois,
                         float* __restrict__ out)
{
    const int n = blockIdx.x;
    __shared__ float pool[NCH];

    // ROI coords (rois are multiples of FEAT_STRIDE, non-negative)
    const int4 rr = ((const int4*)rois)[n];
    const int ymin = rr.x / FEAT_STRIDE;
    const int xmin = rr.y / FEAT_STRIDE;
    const int ymax = rr.z / FEAT_STRIDE;
    const int xmax = rr.w / FEAT_STRIDE;
    const int ystep = (ymax - ymin) / KK;
    const int xstep = (xmax - xmin) / KK;
    const bool has_area = (ystep > 0) && (xstep > 0);
    const float inv_area = has_area ? (1.0f / (float)(ystep * xstep)) : 0.0f;

    for (int c = threadIdx.x; c < NCH; c += blockDim.x) {
        const int g  = c / C1;       // bin index
        const int j  = g / KK;       // bin row
        const int l  = g - j * KK;   // bin col
        float s = 0.0f;
        if (has_area) {
            const int ys = ymin + j * ystep;
            const int xs = xmin + l * xstep;
            const float* p = fmap + (size_t)c * PLANE + ys * WF + xs;
            for (int dy = 0; dy < ystep; ++dy) {
                const float* row = p + dy * WF;
                float rs = 0.0f;
                #pragma unroll 4
                for (int dx = 0; dx < xstep; ++dx)
                    rs += __ldg(row + dx);
                s += rs;
            }
            s *= inv_area;
        }
        pool[c] = s;
    }
    __syncthreads();

    // Per-class mean over 49 bins + softmax over 21 classes (warp 0 only).
    if (threadIdx.x < 32) {
        float v = -1e30f;
        if (threadIdx.x < C1) {
            float s = 0.0f;
            #pragma unroll
            for (int g = 0; g < NBINS; ++g)
                s += pool[g * C1 + threadIdx.x];
            v = s * (1.0f / (float)NBINS);
        }
        // warp max
        float mx = v;
        #pragma unroll
        for (int o = 16; o; o >>= 1)
            mx = fmaxf(mx, __shfl_xor_sync(0xffffffff, mx, o));
        float e = (threadIdx.x < C1) ? __expf(v - mx) : 0.0f;
        float sm = e;
        #pragma unroll
        for (int o = 16; o; o >>= 1)
            sm += __shfl_xor_sync(0xffffffff, sm, o);
        if (threadIdx.x < C1)
            out[n * C1 + threadIdx.x] = e / sm;
    }
}

extern "C" void kernel_launch(void* const* d_in, const int* in_sizes, int n_in,
                              void* d_out, int out_size)
{
    const float* fmap = (const float*)d_in[0];   // (1, 1029, 128, 128) fp32
    const int*   rois = (const int*)d_in[1];     // (N, 4) int32
    float* out = (float*)d_out;                  // (N, 21, 1, 1) fp32
    const int n_rois = in_sizes[1] / 4;

    psroi_scores_kernel<<<n_rois, 256>>>(fmap, rois, out);
}

// round 2
// speedup vs baseline: 3.2160x; 3.2160x over previous
#include <cuda_runtime.h>
#include <cuda_bf16.h>

#define KK 7
#define C1 21
#define NBINS 49            // KK*KK
#define NCH 1029            // NBINS*C1
#define HF 128
#define WF 128
#define PLANE (HF*WF)       // 16384
#define FEAT_STRIDE 30

// Scratch: P[g][y][x][cc] = inclusive prefix sum along x of fmap[(g*21+cc)][y][x]
// size = 49 * 128 * 128 * 21 floats = 16,859,136 floats ~ 67.4 MB
__device__ float g_prefix[NBINS * PLANE * C1];

// ---------------------------------------------------------------------------
// K1: NCHW -> [g][y][x][cc] transpose fused with inclusive prefix-sum along x.
// One block per (g, y). 256 threads (8 warps).
//   read : 21 rows of 128 floats (coalesced, 512B each)
//   scan : warp-shuffle inclusive scan per class row (4 chunks of 32 + carry)
//   write: 21*128 = 2688 floats = 10752 contiguous bytes (fully coalesced)
// ---------------------------------------------------------------------------
__global__ __launch_bounds__(256)
void psroi_transpose_scan_kernel(const float* __restrict__ fmap,
                                 float* __restrict__ P)
{
    const int g = blockIdx.x >> 7;        // bin group 0..48
    const int y = blockIdx.x & 127;       // row 0..127
    const int t = threadIdx.x;
    const int warp = t >> 5;
    const int lane = t & 31;

    __shared__ float tile[C1][WF + 1];    // +1 pad: kills 21-way write-side conflicts

    // Load: 21 * 128 floats, coalesced along x
    #pragma unroll
    for (int idx = t; idx < C1 * WF; idx += 256) {
        const int cc = idx >> 7;          // 0..20
        const int x  = idx & 127;
        tile[cc][x] = fmap[(size_t)(g * C1 + cc) * PLANE + y * WF + x];
    }
    __syncthreads();

    // Inclusive prefix-sum along x for each class row; warp w owns rows w, w+8, ...
    for (int cc = warp; cc < C1; cc += 8) {
        float carry = 0.0f;
        #pragma unroll
        for (int ch = 0; ch < 4; ++ch) {
            float v = tile[cc][ch * 32 + lane];
            #pragma unroll
            for (int d = 1; d < 32; d <<= 1) {
                float u = __shfl_up_sync(0xffffffff, v, d);
                if (lane >= d) v += u;
            }
            v += carry;
            tile[cc][ch * 32 + lane] = v;
            carry = __shfl_sync(0xffffffff, v, 31);
        }
    }
    __syncthreads();

    // Store: contiguous chunk of 2688 floats at base; out idx = x*21 + cc
    float* dst = P + (size_t)(g * PLANE + y * WF) * C1;
    #pragma unroll
    for (int idx = t; idx < C1 * WF; idx += 256) {
        const int x  = idx / C1;
        const int cc = idx - x * C1;
        dst[idx] = tile[cc][x];
    }
}

// ---------------------------------------------------------------------------
// K2: pooling + mean + softmax. One block per ROI, 256 threads (8 warps).
// Warp w handles bins g = w, w+8, ... ; lanes 0..20 = classes.
// Bin-row class sum = P[row][xe-1][cc] - P[row][xs-1][cc]  (84B contiguous reads)
// ---------------------------------------------------------------------------
__global__ __launch_bounds__(256)
void psroi_pool_kernel(const float* __restrict__ P,
                       const int* __restrict__ rois,
                       float* __restrict__ out)
{
    const int n = blockIdx.x;
    const int t = threadIdx.x;
    const int warp = t >> 5;
    const int lane = t & 31;

    __shared__ float pool[NCH];

    const int4 rr = ((const int4*)rois)[n];
    const int ymin = rr.x / FEAT_STRIDE;
    const int xmin = rr.y / FEAT_STRIDE;
    const int ymax = rr.z / FEAT_STRIDE;
    const int xmax = rr.w / FEAT_STRIDE;
    const int ystep = (ymax - ymin) / KK;
    const int xstep = (xmax - xmin) / KK;
    const bool has_area = (ystep > 0) && (xstep > 0);
    const float inv_area = has_area ? (1.0f / (float)(ystep * xstep)) : 0.0f;

    for (int g = warp; g < NBINS; g += 8) {
        float acc = 0.0f;
        if (has_area && lane < C1) {
            const int j  = g / KK;
            const int l  = g - j * KK;
            const int ys = ymin + j * ystep;
            const int xs = xmin + l * xstep;
            const int xe = xs + xstep;                 // exclusive
            const float* rowp = P + ((size_t)(g * PLANE + ys * WF) + (xe - 1)) * C1 + lane;
            const float* rowl = P + ((size_t)(g * PLANE + ys * WF) + (xs - 1)) * C1 + lane;
            for (int dy = 0; dy < ystep; ++dy) {
                float right = __ldg(rowp + dy * WF * C1);
                float left  = (xs > 0) ? __ldg(rowl + dy * WF * C1) : 0.0f;
                acc += right - left;
            }
            acc *= inv_area;
        }
        if (lane < C1) pool[g * C1 + lane] = acc;
    }
    __syncthreads();

    // Per-class mean over 49 bins + softmax over 21 classes (warp 0 only)
    if (t < 32) {
        float v = -1e30f;
        if (t < C1) {
            float s = 0.0f;
            #pragma unroll
            for (int g = 0; g < NBINS; ++g)
                s += pool[g * C1 + t];
            v = s * (1.0f / (float)NBINS);
        }
        float mx = v;
        #pragma unroll
        for (int o = 16; o; o >>= 1)
            mx = fmaxf(mx, __shfl_xor_sync(0xffffffff, mx, o));
        float e = (t < C1) ? __expf(v - mx) : 0.0f;
        float sm = e;
        #pragma unroll
        for (int o = 16; o; o >>= 1)
            sm += __shfl_xor_sync(0xffffffff, sm, o);
        if (t < C1)
            out[n * C1 + t] = e / sm;
    }
}

extern "C" void kernel_launch(void* const* d_in, const int* in_sizes, int n_in,
                              void* d_out, int out_size)
{
    const float* fmap = (const float*)d_in[0];   // (1, 1029, 128, 128) fp32
    const int*   rois = (const int*)d_in[1];     // (N, 4) int32
    float* out = (float*)d_out;                  // (N, 21) fp32
    const int n_rois = in_sizes[1] / 4;

    float* P;
    cudaGetSymbolAddress((void**)&P, g_prefix);

    psroi_transpose_scan_kernel<<<NBINS * HF, 256>>>(fmap, P);
    psroi_pool_kernel<<<n_rois, 256>>>(P, rois, out);
}

// round 3
// speedup vs baseline: 3.5649x; 1.1085x over previous
#include <cuda_runtime.h>
#include <cuda_bf16.h>

#define KK 7
#define C1 21
#define NBINS 49            // KK*KK
#define NCH 1029            // NBINS*C1
#define HF 128
#define WF 128
#define PLANE (HF*WF)       // 16384
#define FEAT_STRIDE 30
#define ROWE (WF*C1)        // elements per [y] row of P: 2688

// Scratch: P[g][y][x][cc] = inclusive prefix sum along x of fmap[(g*21+cc)][y][x]
// 49 * 128 * 128 * 21 floats ~ 67.4 MB
__device__ float g_prefix[NBINS * PLANE * C1];

// ---------------------------------------------------------------------------
// K1: NCHW -> [g][y][x][cc] transpose fused with inclusive x-prefix-sum.
// One block per (g, y), 256 threads (8 warps). Warp w scans class rows
// cc = w, w+8, ... entirely in registers:
//   LDG.128 (4 floats/lane) -> local chain -> warp shuffle-scan of lane sums
//   -> scatter into smem already transposed ([x*21+cc])
// then the block streams smem -> P as contiguous float4 (10752 B / block).
// ---------------------------------------------------------------------------
__global__ __launch_bounds__(256)
void psroi_transpose_scan_kernel(const float* __restrict__ fmap,
                                 float* __restrict__ P)
{
    const int g = blockIdx.x >> 7;        // 0..48
    const int y = blockIdx.x & 127;       // 0..127
    const int t = threadIdx.x;
    const int warp = t >> 5;
    const int lane = t & 31;

    __shared__ float tile2[ROWE];         // [x*21 + cc], 10.5 KB

    for (int cc = warp; cc < C1; cc += 8) {
        const float4* src = (const float4*)(fmap + (size_t)(g * C1 + cc) * PLANE + y * WF);
        float4 v = __ldg(src + lane);
        // local inclusive chain over the 4 elements this lane owns
        float a0 = v.x;
        float a1 = a0 + v.y;
        float a2 = a1 + v.z;
        float a3 = a2 + v.w;
        // inclusive warp scan of lane totals
        float s = a3;
        #pragma unroll
        for (int d = 1; d < 32; d <<= 1) {
            float u = __shfl_up_sync(0xffffffff, s, d);
            if (lane >= d) s += u;
        }
        // exclusive offset for this lane
        float excl = __shfl_up_sync(0xffffffff, s, 1);
        if (lane == 0) excl = 0.0f;

        const int xb = 4 * lane;
        tile2[(xb + 0) * C1 + cc] = excl + a0;
        tile2[(xb + 1) * C1 + cc] = excl + a1;
        tile2[(xb + 2) * C1 + cc] = excl + a2;
        tile2[(xb + 3) * C1 + cc] = excl + a3;
    }
    __syncthreads();

    // contiguous vectorized store: 672 float4
    float4* dst4 = (float4*)(P + (size_t)(g * PLANE + y * WF) * C1);
    const float4* s4 = (const float4*)tile2;
    #pragma unroll
    for (int i = t; i < ROWE / 4; i += 256)
        dst4[i] = s4[i];
}

// ---------------------------------------------------------------------------
// K2: pooling + mean + softmax. One block per ROI, 256 threads (8 warps).
// Warp w owns bins g = w, w+8, ... (<= 7 bins). All bins share ystep/xstep,
// so ONE dy loop services all of them: up to 14 independent 84B loads per
// iteration. Lanes 0..20 = classes.
// ---------------------------------------------------------------------------
__global__ __launch_bounds__(256)
void psroi_pool_kernel(const float* __restrict__ P,
                       const int* __restrict__ rois,
                       float* __restrict__ out)
{
    const int n = blockIdx.x;
    const int t = threadIdx.x;
    const int warp = t >> 5;
    const int lane = t & 31;

    __shared__ float pool[NCH];

    const int4 rr = ((const int4*)rois)[n];
    const int ymin = rr.x / FEAT_STRIDE;
    const int xmin = rr.y / FEAT_STRIDE;
    const int ymax = rr.z / FEAT_STRIDE;
    const int xmax = rr.w / FEAT_STRIDE;
    const int ystep = (ymax - ymin) / KK;
    const int xstep = (xmax - xmin) / KK;
    const bool has_area = (ystep > 0) && (xstep > 0);
    const float inv_area = has_area ? (1.0f / (float)(ystep * xstep)) : 0.0f;

    float acc[7];
    int   offR[7], offL[7];
    bool  bval[7], lval[7];

    #pragma unroll
    for (int b = 0; b < 7; ++b) {
        const int g = warp + b * 8;
        bval[b] = (g < NBINS);
        const int gg = bval[b] ? g : 0;
        const int j  = gg / KK;
        const int l  = gg - j * KK;
        const int ys = ymin + j * ystep;
        const int xs = xmin + l * xstep;
        const int xe = xs + xstep;                       // exclusive
        const int base = gg * (PLANE * C1) + ys * ROWE + lane;
        offR[b] = base + (xe - 1) * C1;
        offL[b] = base + (xs - 1) * C1;
        lval[b] = (xs > 0);
        acc[b]  = 0.0f;
    }

    if (has_area && lane < C1) {
        for (int dy = 0; dy < ystep; ++dy) {
            const int ro = dy * ROWE;
            #pragma unroll
            for (int b = 0; b < 7; ++b) {
                if (bval[b]) {
                    float r  = __ldg(P + offR[b] + ro);
                    float lf = lval[b] ? __ldg(P + offL[b] + ro) : 0.0f;
                    acc[b] += r - lf;
                }
            }
        }
    }

    if (lane < C1) {
        #pragma unroll
        for (int b = 0; b < 7; ++b)
            if (bval[b])
                pool[(warp + b * 8) * C1 + lane] = acc[b] * inv_area;
    }
    __syncthreads();

    // Per-class mean over 49 bins + softmax over 21 classes (warp 0 only)
    if (t < 32) {
        float v = -1e30f;
        if (t < C1) {
            float s = 0.0f;
            #pragma unroll
            for (int g = 0; g < NBINS; ++g)
                s += pool[g * C1 + t];
            v = s * (1.0f / (float)NBINS);
        }
        float mx = v;
        #pragma unroll
        for (int o = 16; o; o >>= 1)
            mx = fmaxf(mx, __shfl_xor_sync(0xffffffff, mx, o));
        float e = (t < C1) ? __expf(v - mx) : 0.0f;
        float sm = e;
        #pragma unroll
        for (int o = 16; o; o >>= 1)
            sm += __shfl_xor_sync(0xffffffff, sm, o);
        if (t < C1)
            out[n * C1 + t] = e / sm;
    }
}

extern "C" void kernel_launch(void* const* d_in, const int* in_sizes, int n_in,
                              void* d_out, int out_size)
{
    const float* fmap = (const float*)d_in[0];   // (1, 1029, 128, 128) fp32
    const int*   rois = (const int*)d_in[1];     // (N, 4) int32
    float* out = (float*)d_out;                  // (N, 21) fp32
    const int n_rois = in_sizes[1] / 4;

    float* P;
    cudaGetSymbolAddress((void**)&P, g_prefix);

    psroi_transpose_scan_kernel<<<NBINS * HF, 256>>>(fmap, P);
    psroi_pool_kernel<<<n_rois, 256>>>(P, rois, out);
}